// round 1
// baseline (speedup 1.0000x reference)
#include <cuda_runtime.h>
#include <cstdint>

#define T_ 512
#define B_ 256
#define D_ 128
#define H_ 256
#define P_ 128
#define M_ (T_*B_)          // 131072 rows for precompute GEMM
#define NBLK 128            // persistent grid size
#define NTHR 256

// ---------------- scratch (static device allocations are allowed) -------------
__device__ float g_A[(size_t)T_*B_*P_];   // 67 MB: precomputed x-part of -log k
__device__ float g_xsq[M_];
__device__ float g_psum[P_];
__device__ float g_h[B_*H_];
__device__ float g_c[B_*H_];
__device__ float g_k[B_*P_];
__device__ unsigned int g_bar_count[2];
__device__ unsigned int g_bar_gen[2];

// ---------------- precompute: row norms of x -------------------------------
__global__ void xsq_kernel(const float* __restrict__ x) {
    int warp = (blockIdx.x * blockDim.x + threadIdx.x) >> 5;
    int lane = threadIdx.x & 31;
    if (warp >= M_) return;
    const float* row = x + (size_t)warp * D_;
    float s = 0.f;
#pragma unroll
    for (int i = 0; i < 4; i++) { float v = row[lane + 32*i]; s += v*v; }
#pragma unroll
    for (int o = 16; o; o >>= 1) s += __shfl_down_sync(0xffffffffu, s, o);
    if (lane == 0) g_xsq[warp] = s;
}

// ---------------- precompute: full row norms of prototypes -----------------
__global__ void psum_kernel(const float* __restrict__ proto) {
    int p = threadIdx.x;
    if (p >= P_) return;
    const float* row = proto + (size_t)p * (D_ + H_);
    float s = 0.f;
    for (int i = 0; i < D_ + H_; i++) { float v = row[i]; s += v*v; }
    g_psum[p] = s;
}

// ---------------- precompute GEMM: A[t,b,p] = xsq + psum - 2*x.px ----------
__global__ void agemm_kernel(const float* __restrict__ x,
                             const float* __restrict__ proto) {
    __shared__ float sX[64][33];
    __shared__ float sP[32][132];
    const int tid = threadIdx.x;
    const int tx = tid & 31;        // -> 4 N columns (tx*4)
    const int ty = tid >> 5;        // -> 8 M rows (ty*8)
    const int m0 = blockIdx.x * 64;

    float acc[8][4];
#pragma unroll
    for (int r = 0; r < 8; r++)
#pragma unroll
        for (int q = 0; q < 4; q++) acc[r][q] = 0.f;

    for (int k0 = 0; k0 < D_; k0 += 32) {
#pragma unroll
        for (int i = 0; i < 8; i++) {
            int e = tid + i * 256;
            int r = e >> 5, c = e & 31;
            sX[r][c] = x[(size_t)(m0 + r) * D_ + k0 + c];
        }
#pragma unroll
        for (int i = 0; i < 16; i++) {
            int e = tid + i * 256;
            int p = e >> 5, c = e & 31;
            sP[c][p] = proto[(size_t)p * (D_ + H_) + k0 + c];
        }
        __syncthreads();
#pragma unroll
        for (int kc = 0; kc < 32; kc++) {
            float4 b4 = *(const float4*)&sP[kc][tx * 4];
#pragma unroll
            for (int r = 0; r < 8; r++) {
                float a = sX[ty * 8 + r][kc];
                acc[r][0] += a * b4.x; acc[r][1] += a * b4.y;
                acc[r][2] += a * b4.z; acc[r][3] += a * b4.w;
            }
        }
        __syncthreads();
    }
#pragma unroll
    for (int r = 0; r < 8; r++) {
        int row = m0 + ty * 8 + r;
        float xs = g_xsq[row];
        float4 o;
        o.x = xs + g_psum[tx*4+0] - 2.f * acc[r][0];
        o.y = xs + g_psum[tx*4+1] - 2.f * acc[r][1];
        o.z = xs + g_psum[tx*4+2] - 2.f * acc[r][2];
        o.w = xs + g_psum[tx*4+3] - 2.f * acc[r][3];
        *(float4*)&g_A[(size_t)row * P_ + tx * 4] = o;
    }
}

// ---------------- global spin barrier (all NBLK blocks resident) -----------
__device__ __forceinline__ void grid_barrier(int which, unsigned int& gen) {
    __threadfence();
    __syncthreads();
    if (threadIdx.x == 0) {
        unsigned int arrived = atomicAdd(&g_bar_count[which], 1u);
        if (arrived == gridDim.x - 1) {
            g_bar_count[which] = 0;
            __threadfence();
            atomicExch(&g_bar_gen[which], gen + 1u);
        } else {
            volatile unsigned int* vg = &g_bar_gen[which];
            while (*vg == gen) { __nanosleep(64); }
        }
        gen = gen + 1u;
    }
    __syncthreads();
}

__device__ __forceinline__ float fsigmoid(float v) {
    return 1.f / (1.f + __expf(-v));
}

// ---------------- main persistent recurrent kernel -------------------------
// smem layout (floats):
//   s_pH  [16][260]   protoH tile (persistent)      4160
//   s_W   [128][128]  gate weight tile (persistent) 16384
//   s_h   [16][260]   current h tile                4160
//   s_k   [16][128]   k tile                        2048
//   s_act [16][128]   activated gates               2048
//   s_hsq [16], s_bias[128]                         144
#define SMEM_FLOATS (4160 + 16384 + 4160 + 2048 + 2048 + 16 + 128)

__global__ void __launch_bounds__(NTHR, 1)
qlstm_main(const float* __restrict__ proto,
           const float* __restrict__ Wf_, const float* __restrict__ bf_,
           const float* __restrict__ Wi_, const float* __restrict__ bi_,
           const float* __restrict__ Wg_, const float* __restrict__ bg_,
           const float* __restrict__ Wo_, const float* __restrict__ bo_,
           float* __restrict__ out) {
    extern __shared__ float sm[];
    float* s_pH   = sm;                       // 16*260
    float* s_W    = s_pH + 16 * 260;          // 128*128
    float* s_h    = s_W + 128 * 128;          // 16*260
    float* s_k    = s_h + 16 * 260;           // 16*128
    float* s_act  = s_k + 16 * 128;           // 16*128
    float* s_hsq  = s_act + 16 * 128;         // 16
    float* s_bias = s_hsq + 16;               // 128

    const int tid = threadIdx.x;
    const int bid = blockIdx.x;
    const int bt  = bid >> 3;   // batch tile 0..15 (16 rows each)
    const int sub = bid & 7;    // role1: p-tile idx; role2: h-chunk idx

    // ---- persistent SMEM fills (once per launch) ----
    // protoH tile: rows p = sub*16..+16, cols = proto[p][128 + j]
    for (int i = tid; i < 16 * 256; i += NTHR) {
        int pl = i >> 8, j = i & 255;
        s_pH[pl * 260 + j] = proto[(size_t)(sub * 16 + pl) * (D_ + H_) + D_ + j];
    }
    // W tile, columns interleaved: jj = gate*32 + ulocal, unit u = sub*32+ulocal
    for (int gate = 0; gate < 4; gate++) {
        const float* Wp = (gate == 0) ? Wf_ : (gate == 1) ? Wi_ : (gate == 2) ? Wg_ : Wo_;
        for (int i = tid; i < 128 * 32; i += NTHR) {
            int p = i & 127, ul = i >> 7;
            s_W[p * 128 + gate * 32 + ul] = Wp[(size_t)(sub * 32 + ul) * P_ + p];
        }
    }
    if (tid < 128) {
        int gate = tid >> 5;
        int u = sub * 32 + (tid & 31);
        const float* bp = (gate == 0) ? bf_ : (gate == 1) ? bi_ : (gate == 2) ? bg_ : bo_;
        s_bias[tid] = bp[u];
    }
    // zero this block's exclusively-owned h/c chunk
    for (int i = tid; i < 512; i += NTHR) {
        int b = i >> 5, u = i & 31;
        int idx = (bt * 16 + b) * H_ + sub * 32 + u;
        g_h[idx] = 0.f;
        g_c[idx] = 0.f;
    }
    __syncthreads();

    unsigned int genA = 0, genB = 0;
    if (tid == 0) {
        genA = atomicAdd(&g_bar_gen[0], 0u);
        genB = atomicAdd(&g_bar_gen[1], 0u);
    }
    grid_barrier(0, genA);   // h/c init visible everywhere

    const int bl1 = tid >> 4;   // 0..15: b within tile (role1)
    const int pl1 = tid & 15;   // 0..15: p within tile (role1)
    const size_t OUT_H = (size_t)T_ * B_ * H_;

#pragma unroll 1
    for (int t = 0; t < T_; t++) {
        // ============ phase 1: k tile (bt, sub) ============
        for (int i = tid; i < 16 * 256; i += NTHR) {
            int b = i >> 8, j = i & 255;
            s_h[b * 260 + j] = __ldcg(&g_h[(bt * 16 + b) * H_ + j]);
        }
        __syncthreads();
        // hsq: 16 lanes cooperate per b row
        {
            float s = 0.f;
            const float* hp = &s_h[bl1 * 260 + pl1 * 16];
#pragma unroll
            for (int j = 0; j < 16; j++) { float v = hp[j]; s += v * v; }
#pragma unroll
            for (int o = 8; o; o >>= 1) s += __shfl_down_sync(0xffffffffu, s, o, 16);
            if (pl1 == 0) s_hsq[bl1] = s;
        }
        float dot = 0.f;
        {
            const float* hp = &s_h[bl1 * 260];
            const float* pp = &s_pH[pl1 * 260];
#pragma unroll 8
            for (int j = 0; j < 256; j += 4) {
                float4 hv = *(const float4*)(hp + j);
                float4 pv = *(const float4*)(pp + j);
                dot += hv.x * pv.x + hv.y * pv.y + hv.z * pv.z + hv.w * pv.w;
            }
        }
        __syncthreads();   // s_hsq ready
        {
            int b = bt * 16 + bl1;
            int p = sub * 16 + pl1;
            float a = g_A[((size_t)t * B_ + b) * P_ + p];
            float kk = __expf(-(a + s_hsq[bl1] - 2.f * dot));
            g_k[b * P_ + p] = kk;
        }
        grid_barrier(1, genB);   // k complete

        // ============ phase 2: gates + state update (bt, sub) ============
        for (int i = tid; i < 16 * 128; i += NTHR) {
            s_k[i] = __ldcg(&g_k[(bt * 16 + (i >> 7)) * P_ + (i & 127)]);
        }
        __syncthreads();
        {
            const int j0 = (tid & 31) * 4;   // 4 gate columns
            const int brow = tid >> 5;       // rows brow, brow+8
            float acc0[4] = {s_bias[j0], s_bias[j0+1], s_bias[j0+2], s_bias[j0+3]};
            float acc1[4] = {acc0[0], acc0[1], acc0[2], acc0[3]};
            const float* k0p = &s_k[brow * 128];
            const float* k1p = &s_k[(brow + 8) * 128];
#pragma unroll 4
            for (int p = 0; p < 128; p++) {
                float4 w = *(const float4*)&s_W[p * 128 + j0];
                float ka = k0p[p], kb = k1p[p];
                acc0[0] += ka * w.x; acc0[1] += ka * w.y;
                acc0[2] += ka * w.z; acc0[3] += ka * w.w;
                acc1[0] += kb * w.x; acc1[1] += kb * w.y;
                acc1[2] += kb * w.z; acc1[3] += kb * w.w;
            }
            const int gate = j0 >> 5;   // uniform over the 4 columns
            float4 r0, r1;
            if (gate == 2) {
                r0.x = tanhf(acc0[0]); r0.y = tanhf(acc0[1]);
                r0.z = tanhf(acc0[2]); r0.w = tanhf(acc0[3]);
                r1.x = tanhf(acc1[0]); r1.y = tanhf(acc1[1]);
                r1.z = tanhf(acc1[2]); r1.w = tanhf(acc1[3]);
            } else {
                r0.x = fsigmoid(acc0[0]); r0.y = fsigmoid(acc0[1]);
                r0.z = fsigmoid(acc0[2]); r0.w = fsigmoid(acc0[3]);
                r1.x = fsigmoid(acc1[0]); r1.y = fsigmoid(acc1[1]);
                r1.z = fsigmoid(acc1[2]); r1.w = fsigmoid(acc1[3]);
            }
            *(float4*)&s_act[brow * 128 + j0] = r0;
            *(float4*)&s_act[(brow + 8) * 128 + j0] = r1;
        }
        __syncthreads();
        {
            const int u = tid & 31;
#pragma unroll
            for (int hh = 0; hh < 2; hh++) {
                int b = (tid >> 5) + hh * 8;
                float f  = s_act[b * 128 + u];
                float ii = s_act[b * 128 + 32 + u];
                float gg = s_act[b * 128 + 64 + u];
                float oo = s_act[b * 128 + 96 + u];
                int idx = (bt * 16 + b) * H_ + sub * 32 + u;
                float c = g_c[idx];
                c = f * c + ii * gg;
                float h = oo * tanhf(c);
                g_c[idx] = c;
                g_h[idx] = h;
                out[(size_t)t * (B_ * H_) + idx] = h;
                if (t == T_ - 1) {
                    out[OUT_H + idx] = h;                 // hx
                    out[OUT_H + (size_t)B_ * H_ + idx] = c; // cx
                }
            }
        }
        grid_barrier(0, genA);   // h complete
    }
}

// ---------------- launch ----------------------------------------------------
extern "C" void kernel_launch(void* const* d_in, const int* in_sizes, int n_in,
                              void* d_out, int out_size) {
    const float* x     = (const float*)d_in[0];
    const float* proto = (const float*)d_in[1];
    const float* Wf    = (const float*)d_in[2];
    const float* bf    = (const float*)d_in[3];
    const float* Wi    = (const float*)d_in[4];
    const float* bi    = (const float*)d_in[5];
    const float* Wg    = (const float*)d_in[6];
    const float* bg    = (const float*)d_in[7];
    const float* Wo    = (const float*)d_in[8];
    const float* bo    = (const float*)d_in[9];
    float* out = (float*)d_out;

    const int smem_bytes = SMEM_FLOATS * (int)sizeof(float);
    cudaFuncSetAttribute(qlstm_main, cudaFuncAttributeMaxDynamicSharedMemorySize,
                         smem_bytes);

    xsq_kernel<<<M_ / 8, 256>>>(x);
    psum_kernel<<<1, 128>>>(proto);
    agemm_kernel<<<M_ / 64, 256>>>(x, proto);
    qlstm_main<<<NBLK, NTHR, smem_bytes>>>(proto, Wf, bf, Wi, bi, Wg, bg, Wo, bo, out);
}

// round 4
// speedup vs baseline: 1.9488x; 1.9488x over previous
#include <cuda_runtime.h>
#include <cstdint>

#define T_ 512
#define B_ 256
#define D_ 128
#define H_ 256
#define P_ 128
#define M_ (T_*B_)
#define NBLK 128
#define NTHR 256
#define BH_ (B_*H_)

typedef unsigned long long ull;

// ---------------- scratch ---------------------------------------------------
__device__ float g_A[(size_t)T_*B_*P_];   // precomputed x-part of distance
__device__ float g_xsq[M_];
__device__ float g_psum[P_];
__device__ float g_h[BH_];
__device__ float g_kT[16*128*16];         // [group][p][b]
__device__ unsigned int g_cnt[2*16*32];   // 2 barriers x 16 groups, 128B apart

// ---------------- f32x2 helpers --------------------------------------------
__device__ __forceinline__ ull pack2(float lo, float hi) {
    ull r; asm("mov.b64 %0, {%1, %2};" : "=l"(r) : "f"(lo), "f"(hi)); return r;
}
__device__ __forceinline__ void unpack2(ull v, float& lo, float& hi) {
    asm("mov.b64 {%0, %1}, %2;" : "=f"(lo), "=f"(hi) : "l"(v));
}
__device__ __forceinline__ ull fma2(ull a, ull b, ull c) {
    ull d; asm("fma.rn.f32x2 %0, %1, %2, %3;" : "=l"(d) : "l"(a), "l"(b), "l"(c));
    return d;
}
__device__ __forceinline__ float sigf(float x) {
    return __fdividef(1.f, 1.f + __expf(-x));
}
__device__ __forceinline__ float tanh_fast(float x) {
    float e = __expf(2.f * x);
    return 1.f - __fdividef(2.f, e + 1.f);
}

// ---------------- precompute: row norms of x -------------------------------
__global__ void xsq_kernel(const float* __restrict__ x) {
    int warp = (blockIdx.x * blockDim.x + threadIdx.x) >> 5;
    int lane = threadIdx.x & 31;
    if (warp >= M_) return;
    const float* row = x + (size_t)warp * D_;
    float s = 0.f;
#pragma unroll
    for (int i = 0; i < 4; i++) { float v = row[lane + 32*i]; s += v*v; }
#pragma unroll
    for (int o = 16; o; o >>= 1) s += __shfl_down_sync(0xffffffffu, s, o);
    if (lane == 0) g_xsq[warp] = s;
}

// ---------------- precompute: full row norms of prototypes -----------------
__global__ void psum_kernel(const float* __restrict__ proto) {
    int p = threadIdx.x;
    if (p >= P_) return;
    const float* row = proto + (size_t)p * (D_ + H_);
    float s = 0.f;
    for (int i = 0; i < D_ + H_; i++) { float v = row[i]; s += v*v; }
    g_psum[p] = s;
}

// ---------------- precompute GEMM: A[t,b,p] = xsq + psum - 2*x.px ----------
__global__ void agemm_kernel(const float* __restrict__ x,
                             const float* __restrict__ proto) {
    __shared__ float sX[64][33];
    __shared__ float sP[32][132];
    const int tid = threadIdx.x;
    const int tx = tid & 31;
    const int ty = tid >> 5;
    const int m0 = blockIdx.x * 64;

    float acc[8][4];
#pragma unroll
    for (int r = 0; r < 8; r++)
#pragma unroll
        for (int q = 0; q < 4; q++) acc[r][q] = 0.f;

    for (int k0 = 0; k0 < D_; k0 += 32) {
#pragma unroll
        for (int i = 0; i < 8; i++) {
            int e = tid + i * 256;
            int r = e >> 5, c = e & 31;
            sX[r][c] = x[(size_t)(m0 + r) * D_ + k0 + c];
        }
#pragma unroll
        for (int i = 0; i < 16; i++) {
            int e = tid + i * 256;
            int p = e >> 5, c = e & 31;
            sP[c][p] = proto[(size_t)p * (D_ + H_) + k0 + c];
        }
        __syncthreads();
#pragma unroll
        for (int kc = 0; kc < 32; kc++) {
            float4 b4 = *(const float4*)&sP[kc][tx * 4];
#pragma unroll
            for (int r = 0; r < 8; r++) {
                float a = sX[ty * 8 + r][kc];
                acc[r][0] += a * b4.x; acc[r][1] += a * b4.y;
                acc[r][2] += a * b4.z; acc[r][3] += a * b4.w;
            }
        }
        __syncthreads();
    }
#pragma unroll
    for (int r = 0; r < 8; r++) {
        int row = m0 + ty * 8 + r;
        float xs = g_xsq[row];
        float4 o;
        o.x = xs + g_psum[tx*4+0] - 2.f * acc[r][0];
        o.y = xs + g_psum[tx*4+1] - 2.f * acc[r][1];
        o.z = xs + g_psum[tx*4+2] - 2.f * acc[r][2];
        o.w = xs + g_psum[tx*4+3] - 2.f * acc[r][3];
        *(float4*)&g_A[(size_t)row * P_ + tx * 4] = o;
    }
}

// ---------------- counter reset (stream-ordered, before main) --------------
__global__ void zero_cnt_kernel() {
    int i = threadIdx.x;
    if (i < 2*16*32) g_cnt[i] = 0;
}

// ---------------- group barrier: 8 blocks of one batch tile ----------------
__device__ __forceinline__ void group_barrier(unsigned int* cnt, unsigned int target) {
    __syncthreads();
    if (threadIdx.x == 0) {
        __threadfence();
        atomicAdd(cnt, 1u);
        unsigned int v;
        do {
            asm volatile("ld.acquire.gpu.global.u32 %0, [%1];"
                         : "=r"(v) : "l"(cnt) : "memory");
        } while (v < target);
    }
    __syncthreads();
}

// ---------------- main persistent recurrent kernel -------------------------
// smem floats: s_pH 16*260 | s_W 128*128 | s_h 16*260 | s_kT2 128*16*2 | s_hsq 16
#define SMEM_FLOATS (4160 + 16384 + 4160 + 4096 + 16)

__global__ void __launch_bounds__(NTHR, 1)
qlstm_main(const float* __restrict__ proto,
           const float* __restrict__ Wf_, const float* __restrict__ bf_,
           const float* __restrict__ Wi_, const float* __restrict__ bi_,
           const float* __restrict__ Wg_, const float* __restrict__ bg_,
           const float* __restrict__ Wo_, const float* __restrict__ bo_,
           float* __restrict__ out) {
    extern __shared__ float sm[];
    float* s_pH  = sm;                    // 16*260
    float* s_W   = s_pH + 16 * 260;       // 128*128  (layout [p][unit*4+gate])
    float* s_h   = s_W + 128 * 128;       // 16*260
    float* s_kT2 = s_h + 16 * 260;        // [p][b][2] duplicated k
    float* s_hsq = s_kT2 + 4096;          // 16

    const int tid = threadIdx.x;
    const int bid = blockIdx.x;
    const int bt  = bid >> 3;   // batch tile 0..15
    const int sub = bid & 7;    // p-tile (phase1) / unit-chunk (phase2)

    // phase-1 mapping
    const int bl1 = tid >> 4;
    const int pl1 = tid & 15;
    // phase-2 mapping: warp covers 8 units x 8 rows; lane = 2 rows x 1 unit
    const int w    = tid >> 5;
    const int lane = tid & 31;
    const int rh   = w >> 2;                 // row half
    const int uq   = w & 3;                  // unit quarter
    const int unit = uq * 8 + (lane & 7);    // 0..31
    const int rr   = lane >> 3;              // 0..3
    const int row0 = rh * 8 + rr * 2;
    const int row1 = row0 + 1;
    const int gu   = sub * 32 + unit;
    const int idx0 = (bt * 16 + row0) * H_ + gu;
    const int idx1 = (bt * 16 + row1) * H_ + gu;

    // ---- persistent SMEM fills ----
    for (int i = tid; i < 16 * 256; i += NTHR) {
        int pl = i >> 8, j = i & 255;
        s_pH[pl * 260 + j] = proto[(size_t)(sub * 16 + pl) * (D_ + H_) + D_ + j];
    }
#pragma unroll
    for (int g = 0; g < 4; g++) {
        const float* Wp = (g == 0) ? Wf_ : (g == 1) ? Wi_ : (g == 2) ? Wg_ : Wo_;
        for (int i = tid; i < 128 * 32; i += NTHR) {
            int p = i & 127, ul = i >> 7;
            s_W[p * 128 + ul * 4 + g] = Wp[(size_t)(sub * 32 + ul) * P_ + p];
        }
    }
    const ull bfi = pack2(bf_[gu], bi_[gu]);
    const ull bgo = pack2(bg_[gu], bo_[gu]);

    float c0 = 0.f, c1 = 0.f, h0v = 0.f, h1v = 0.f;
    g_h[idx0] = 0.f;
    g_h[idx1] = 0.f;
    __syncthreads();

    unsigned int* k_cnt = &g_cnt[(0 * 16 + bt) * 32];
    unsigned int* h_cnt = &g_cnt[(1 * 16 + bt) * 32];

    group_barrier(h_cnt, 8u);   // h/c zeros visible inside group

    const size_t OUT_H = (size_t)T_ * BH_;

#pragma unroll 1
    for (int t = 0; t < T_; t++) {
        // ================= phase 1: k tile (16 b x 16 p) =================
        {
            const float4* gh4 = (const float4*)g_h;
            for (int i = tid; i < 1024; i += NTHR) {
                int b = i >> 6, q = i & 63;
                float4 v = __ldcg(&gh4[(size_t)(bt * 16 + b) * 64 + q]);
                *(float4*)&s_h[b * 260 + q * 4] = v;
            }
            float a_pre = __ldcg(&g_A[((size_t)t * B_ + bt * 16 + bl1) * P_ +
                                      sub * 16 + pl1]);
            __syncthreads();

            // hsq: 16-lane cooperative reduction per row
            {
                float s = 0.f;
                const float4* hp4 = (const float4*)&s_h[bl1 * 260 + pl1 * 16];
#pragma unroll
                for (int q = 0; q < 4; q++) {
                    float4 v = hp4[q];
                    s += v.x*v.x + v.y*v.y + v.z*v.z + v.w*v.w;
                }
#pragma unroll
                for (int o = 8; o; o >>= 1)
                    s += __shfl_down_sync(0xffffffffu, s, o, 16);
                if (pl1 == 0) s_hsq[bl1] = s;
            }
            // dot(h_row, pH_row) with packed f32x2
            ull acc2a = 0ull, acc2b = 0ull;
            const float* hp = &s_h[bl1 * 260];
            const float* pp = &s_pH[pl1 * 260];
#pragma unroll 8
            for (int j = 0; j < 256; j += 4) {
                ulonglong2 hv = *(const ulonglong2*)(hp + j);
                ulonglong2 pv = *(const ulonglong2*)(pp + j);
                acc2a = fma2(hv.x, pv.x, acc2a);
                acc2b = fma2(hv.y, pv.y, acc2b);
            }
            float dx, dy, dz, dw;
            unpack2(acc2a, dx, dy); unpack2(acc2b, dz, dw);
            float dot = (dx + dy) + (dz + dw);
            __syncthreads();
            float d2 = a_pre + s_hsq[bl1] - 2.f * dot;
            g_kT[(size_t)(bt * 128 + sub * 16 + pl1) * 16 + bl1] = __expf(-d2);
        }
        group_barrier(k_cnt, 8u * (unsigned)(t + 1));

        // ================= phase 2: gates + state update =================
        {
            const float4* gk4 = (const float4*)g_kT;
            for (int i = tid; i < 512; i += NTHR) {
                float4 v = __ldcg(&gk4[(size_t)bt * 512 + i]);
                *(float4*)&s_kT2[i * 8 + 0] = make_float4(v.x, v.x, v.y, v.y);
                *(float4*)&s_kT2[i * 8 + 4] = make_float4(v.z, v.z, v.w, v.w);
            }
            __syncthreads();

            ull afi0 = bfi, ago0 = bgo, afi1 = bfi, ago1 = bgo;
#pragma unroll 8
            for (int p = 0; p < 128; p++) {
                ulonglong2 w2 = *(const ulonglong2*)&s_W[p * 128 + unit * 4];
                ull k0 = *(const ull*)&s_kT2[(p * 16 + row0) * 2];
                ull k1 = *(const ull*)&s_kT2[(p * 16 + row1) * 2];
                afi0 = fma2(k0, w2.x, afi0);
                ago0 = fma2(k0, w2.y, ago0);
                afi1 = fma2(k1, w2.x, afi1);
                ago1 = fma2(k1, w2.y, ago1);
            }
            float vf, vi, vg, vo;
            unpack2(afi0, vf, vi); unpack2(ago0, vg, vo);
            {
                float f = sigf(vf), ii = sigf(vi), gg = tanh_fast(vg), o = sigf(vo);
                c0 = f * c0 + ii * gg;
                h0v = o * tanh_fast(c0);
                g_h[idx0] = h0v;
                out[(size_t)t * BH_ + idx0] = h0v;
            }
            unpack2(afi1, vf, vi); unpack2(ago1, vg, vo);
            {
                float f = sigf(vf), ii = sigf(vi), gg = tanh_fast(vg), o = sigf(vo);
                c1 = f * c1 + ii * gg;
                h1v = o * tanh_fast(c1);
                g_h[idx1] = h1v;
                out[(size_t)t * BH_ + idx1] = h1v;
            }
        }
        group_barrier(h_cnt, 8u * (unsigned)(t + 2));
    }

    // final hx / cx
    out[OUT_H + idx0] = h0v;
    out[OUT_H + BH_ + idx0] = c0;
    out[OUT_H + idx1] = h1v;
    out[OUT_H + BH_ + idx1] = c1;
}

// ---------------- launch ----------------------------------------------------
extern "C" void kernel_launch(void* const* d_in, const int* in_sizes, int n_in,
                              void* d_out, int out_size) {
    const float* x     = (const float*)d_in[0];
    const float* proto = (const float*)d_in[1];
    const float* Wf    = (const float*)d_in[2];
    const float* bf    = (const float*)d_in[3];
    const float* Wi    = (const float*)d_in[4];
    const float* bi    = (const float*)d_in[5];
    const float* Wg    = (const float*)d_in[6];
    const float* bg    = (const float*)d_in[7];
    const float* Wo    = (const float*)d_in[8];
    const float* bo    = (const float*)d_in[9];
    float* out = (float*)d_out;

    const int smem_bytes = SMEM_FLOATS * (int)sizeof(float);
    cudaFuncSetAttribute(qlstm_main, cudaFuncAttributeMaxDynamicSharedMemorySize,
                         smem_bytes);

    zero_cnt_kernel<<<1, 1024>>>();
    xsq_kernel<<<M_ / 8, 256>>>(x);
    psum_kernel<<<1, 128>>>(proto);
    agemm_kernel<<<M_ / 64, 256>>>(x, proto);
    qlstm_main<<<NBLK, NTHR, smem_bytes>>>(proto, Wf, bf, Wi, bi, Wg, bg, Wo, bo, out);
}